// round 4
// baseline (speedup 1.0000x reference)
#include <cuda_runtime.h>
#include <cuda_fp16.h>
#include <mma.h>
#include <math.h>

using namespace nvcuda;

#define NMAX 100000
#define EMAX 1600000

// ---------------- device scratch ----------------
__device__ float  g_dinv[NMAX];
__device__ int    g_cnt[NMAX];
__device__ int    g_fill[NMAX];
__device__ int    g_rowptr[NMAX + 1];
__device__ int    g_bsum[256];
__device__ int    g_col[EMAX];
__device__ __half g_hA[(size_t)NMAX * 128];
__device__ __half g_hB[(size_t)NMAX * 128];
__device__ __half g_hH2[(size_t)NMAX * 128];

// ---------------- CSR build ----------------
__global__ void zero_counts_kernel(int n) {
    int i = blockIdx.x * blockDim.x + threadIdx.x;
    if (i < n) { g_cnt[i] = 0; g_fill[i] = 0; }
}

__global__ void count_edges_kernel(const int* __restrict__ dst, int e) {
    int i = blockIdx.x * blockDim.x + threadIdx.x;
    if (i < e) atomicAdd(&g_cnt[dst[i]], 1);
}

__global__ void scan1_kernel(int n) {
    __shared__ int s[1024];
    int tid = threadIdx.x;
    int i = blockIdx.x * 1024 + tid;
    int v = (i < n) ? g_cnt[i] : 0;
    s[tid] = v;
    __syncthreads();
    for (int off = 1; off < 1024; off <<= 1) {
        int t2 = (tid >= off) ? s[tid - off] : 0;
        __syncthreads();
        s[tid] += t2;
        __syncthreads();
    }
    if (i < n) {
        g_rowptr[i] = s[tid] - v;
        g_dinv[i] = rsqrtf((float)(v + 1));
    }
    if (tid == 1023) g_bsum[blockIdx.x] = s[1023];
}

__global__ void scan2_kernel(int nb) {
    __shared__ int s[128];
    int tid = threadIdx.x;
    int v = (tid < nb) ? g_bsum[tid] : 0;
    s[tid] = v;
    __syncthreads();
    for (int off = 1; off < 128; off <<= 1) {
        int t2 = (tid >= off) ? s[tid - off] : 0;
        __syncthreads();
        s[tid] += t2;
        __syncthreads();
    }
    if (tid < nb) g_bsum[tid] = s[tid] - v;
    if (tid == 127) g_bsum[nb] = s[127];
}

__global__ void scan3_kernel(int n, int nb) {
    int i = blockIdx.x * blockDim.x + threadIdx.x;
    if (i < n) g_rowptr[i] += g_bsum[i >> 10];
    if (i == 0) g_rowptr[n] = g_bsum[nb];
}

__global__ void scatter_edges_kernel(const int* __restrict__ src,
                                     const int* __restrict__ dst, int e) {
    int i = blockIdx.x * blockDim.x + threadIdx.x;
    if (i < e) {
        int d = dst[i];
        int p = g_rowptr[d] + atomicAdd(&g_fill[d], 1);
        g_col[p] = src[i];
    }
}

// ---------------- device helper: gather 8 features of one node ----------------
// acc = hs[v] + sum_{u in nbr(v)} hs[u]   (8 halfs at column c, fp32 accum)
__device__ __forceinline__ void gather8(const __half* __restrict__ hs, int v,
                                        int c, int D, float* acc) {
    const uint4* base = (const uint4*)hs;
    size_t selfidx = ((size_t)v * D + c) >> 3;
    {
        uint4 sv = base[selfidx];
        const __half2* h = (const __half2*)&sv;
#pragma unroll
        for (int q = 0; q < 4; q++) {
            float2 f = __half22float2(h[q]);
            acc[2 * q] = f.x; acc[2 * q + 1] = f.y;
        }
    }
    float acc2[8] = {0, 0, 0, 0, 0, 0, 0, 0};
    int beg = g_rowptr[v], end = g_rowptr[v + 1];
    int e = beg;
    for (; e + 1 < end; e += 2) {
        int u0 = g_col[e], u1 = g_col[e + 1];
        uint4 m0 = base[((size_t)u0 * D + c) >> 3];
        uint4 m1 = base[((size_t)u1 * D + c) >> 3];
        const __half2* h0 = (const __half2*)&m0;
        const __half2* h1 = (const __half2*)&m1;
#pragma unroll
        for (int q = 0; q < 4; q++) {
            float2 f0 = __half22float2(h0[q]);
            float2 f1 = __half22float2(h1[q]);
            acc[2 * q] += f0.x; acc2[2 * q] += f1.x;
            acc[2 * q + 1] += f0.y; acc2[2 * q + 1] += f1.y;
        }
    }
    if (e < end) {
        int u = g_col[e];
        uint4 m = base[((size_t)u * D + c) >> 3];
        const __half2* h = (const __half2*)&m;
#pragma unroll
        for (int q = 0; q < 4; q++) {
            float2 f = __half22float2(h[q]);
            acc[2 * q] += f.x;
            acc[2 * q + 1] += f.y;
        }
    }
#pragma unroll
    for (int q = 0; q < 8; q++) acc[q] += acc2[q];
}

// ---------------- fused agg + GEMM ----------------
// For 128 nodes: t[v] = relu(dinv[v]*gather(hs) + bias_in); a[v] = dinv[v]*t[v]
// out rows = a @ W  (D x D), stored half.  256 threads / 8 warps.
template <int D>
__global__ __launch_bounds__(256) void fused_agg_gemm_kernel(
    const __half* __restrict__ hs, const float* __restrict__ bias_in,
    const float* __restrict__ W, __half* __restrict__ out, int n) {
    constexpr int LDA = D + 8;
    constexpr int LDW = D + 8;
    constexpr int LDS_ = D + 4;
    extern __shared__ char smraw[];
    __half* As = (__half*)smraw;
    __half* Ws = (__half*)(smraw + (size_t)128 * LDA * 2);
    float*  St = (float*)smraw;

    const int t = threadIdx.x;
    const int w = t >> 5;
    const int row0 = blockIdx.x * 128;

    // load W [D][D] fp32 -> half smem
    for (int idx = t; idx < D * D / 4; idx += 256) {
        int k = idx / (D / 4);
        int j = (idx % (D / 4)) * 4;
        const float* sp = W + (size_t)k * D + j;
        Ws[k * LDW + j + 0] = __float2half(sp[0]);
        Ws[k * LDW + j + 1] = __float2half(sp[1]);
        Ws[k * LDW + j + 2] = __float2half(sp[2]);
        Ws[k * LDW + j + 3] = __float2half(sp[3]);
    }

    // gather phase
    constexpr int LPN = D / 8;          // lanes per node
    constexpr int NPI = 256 / LPN;      // nodes per iteration
    const int lane = t % LPN;
    const int c = lane * 8;
#pragma unroll
    for (int it = 0; it < 128 / NPI; it++) {
        int r = it * NPI + t / LPN;
        int v = row0 + r;
        __half hv[8];
        if (v < n) {
            float acc[8];
            gather8(hs, v, c, D, acc);
            float s = g_dinv[v];
            float4 b0 = *(const float4*)(bias_in + c);
            float4 b1 = *(const float4*)(bias_in + c + 4);
            float bb[8] = {b0.x, b0.y, b0.z, b0.w, b1.x, b1.y, b1.z, b1.w};
#pragma unroll
            for (int q = 0; q < 8; q++) {
                float tv = fmaxf(s * acc[q] + bb[q], 0.f);  // relu
                hv[q] = __float2half(s * tv);                // next-gemm dinv scale
            }
        } else {
#pragma unroll
            for (int q = 0; q < 8; q++) hv[q] = __float2half(0.f);
        }
        *(uint4*)&As[r * LDA + c] = *(uint4*)hv;
    }
    __syncthreads();

    // mma: 8 warps, each 16 rows x D cols
    wmma::fragment<wmma::accumulator, 16, 16, 16, float> acc[D / 16];
#pragma unroll
    for (int j = 0; j < D / 16; j++) wmma::fill_fragment(acc[j], 0.f);
    for (int k = 0; k < D; k += 16) {
        wmma::fragment<wmma::matrix_a, 16, 16, 16, __half, wmma::row_major> af;
        wmma::load_matrix_sync(af, As + (w * 16) * LDA + k, LDA);
#pragma unroll
        for (int j = 0; j < D / 16; j++) {
            wmma::fragment<wmma::matrix_b, 16, 16, 16, __half, wmma::row_major> bf;
            wmma::load_matrix_sync(bf, Ws + k * LDW + j * 16, LDW);
            wmma::mma_sync(acc[j], af, bf, acc[j]);
        }
    }
    __syncthreads();
#pragma unroll
    for (int j = 0; j < D / 16; j++)
        wmma::store_matrix_sync(St + (w * 16) * LDS_ + j * 16, acc[j], LDS_,
                                wmma::mem_row_major);
    __syncthreads();

    // epilogue: float -> half store
    constexpr int LANES = D / 8;
    const int el = t % LANES;
    const int rsub = t / LANES;
#pragma unroll
    for (int g = 0; g < 128 / (256 / LANES); g++) {
        int r = g * (256 / LANES) + rsub;
        int gr = row0 + r;
        if (gr >= n) continue;
        const float* sp = St + r * LDS_ + el * 8;
        __half hv[8];
#pragma unroll
        for (int q = 0; q < 8; q++) hv[q] = __float2half(sp[q]);
        *(uint4*)((__half*)out + (size_t)gr * D + el * 8) = *(uint4*)hv;
    }
}

// ---------------- final fused: agg(label) + concat(h2) + GEMM(Wf) + sigmoid ----
__global__ __launch_bounds__(256) void final_fused_kernel(
    const __half* __restrict__ hsL, const float* __restrict__ biasL,
    const __half* __restrict__ h2, const float* __restrict__ Wf,
    const float* __restrict__ bf, float* __restrict__ out, int n) {
    constexpr int K = 192, DN = 64, LDA = K + 8, LDW = DN + 8, LDS_ = DN + 4;
    extern __shared__ char smraw[];
    __half* As = (__half*)smraw;
    __half* Ws = (__half*)(smraw + (size_t)128 * LDA * 2);
    float*  St = (float*)smraw;

    const int t = threadIdx.x;
    const int w = t >> 5;
    const int row0 = blockIdx.x * 128;

    // load Wf [192][64] fp32 -> half
    for (int idx = t; idx < K * DN / 4; idx += 256) {
        int k = idx / (DN / 4);
        int j = (idx % (DN / 4)) * 4;
        const float* sp = Wf + (size_t)k * DN + j;
        Ws[k * LDW + j + 0] = __float2half(sp[0]);
        Ws[k * LDW + j + 1] = __float2half(sp[1]);
        Ws[k * LDW + j + 2] = __float2half(sp[2]);
        Ws[k * LDW + j + 3] = __float2half(sp[3]);
    }

    // load h2 rows into As[:, 0:128]
    for (int idx = t; idx < 128 * 16; idx += 256) {
        int r = idx / 16;
        int q = (idx % 16) * 8;
        int gr = row0 + r;
        uint4 v = make_uint4(0, 0, 0, 0);
        if (gr < n) v = *(const uint4*)(h2 + (size_t)gr * 128 + q);
        *(uint4*)&As[r * LDA + q] = v;
    }

    // gather label part into As[:, 128:192]  (no relu, no dinv-out scale)
    {
        const int lane = t % 8;
        const int c = lane * 8;
#pragma unroll
        for (int it = 0; it < 4; it++) {
            int r = it * 32 + t / 8;
            int v = row0 + r;
            __half hv[8];
            if (v < n) {
                float acc[8];
                gather8(hsL, v, c, 64, acc);
                float s = g_dinv[v];
                float4 b0 = *(const float4*)(biasL + c);
                float4 b1 = *(const float4*)(biasL + c + 4);
                float bb[8] = {b0.x, b0.y, b0.z, b0.w, b1.x, b1.y, b1.z, b1.w};
#pragma unroll
                for (int q = 0; q < 8; q++)
                    hv[q] = __float2half(s * acc[q] + bb[q]);
            } else {
#pragma unroll
                for (int q = 0; q < 8; q++) hv[q] = __float2half(0.f);
            }
            *(uint4*)&As[r * LDA + 128 + c] = *(uint4*)hv;
        }
    }
    __syncthreads();

    wmma::fragment<wmma::accumulator, 16, 16, 16, float> acc[4];
#pragma unroll
    for (int j = 0; j < 4; j++) wmma::fill_fragment(acc[j], 0.f);
    for (int k = 0; k < K; k += 16) {
        wmma::fragment<wmma::matrix_a, 16, 16, 16, __half, wmma::row_major> af;
        wmma::load_matrix_sync(af, As + (w * 16) * LDA + k, LDA);
#pragma unroll
        for (int j = 0; j < 4; j++) {
            wmma::fragment<wmma::matrix_b, 16, 16, 16, __half, wmma::row_major> bf_;
            wmma::load_matrix_sync(bf_, Ws + k * LDW + j * 16, LDW);
            wmma::mma_sync(acc[j], af, bf_, acc[j]);
        }
    }
    __syncthreads();
#pragma unroll
    for (int j = 0; j < 4; j++)
        wmma::store_matrix_sync(St + (w * 16) * LDS_ + j * 16, acc[j], LDS_,
                                wmma::mem_row_major);
    __syncthreads();

    const int el = t % 8;
    const int rsub = t / 8;
#pragma unroll
    for (int g = 0; g < 4; g++) {
        int r = g * 32 + rsub;
        int gr = row0 + r;
        if (gr >= n) continue;
        const float* sp = St + r * LDS_ + el * 8;
        const float* bp = bf + el * 8;
        float ov[8];
#pragma unroll
        for (int q = 0; q < 8; q++)
            ov[q] = 1.f / (1.f + __expf(-(sp[q] + bp[q])));
        float* outp = out + (size_t)gr * 64 + el * 8;
        *(float4*)outp = *(float4*)ov;
        *(float4*)(outp + 4) = *(float4*)(ov + 4);
    }
}

// ---------------- first-layer GEMM (fp32 A input, dinv pre-scale, half out) ----
#define GBM 128
#define GBN 64

template <int K, int C>
__global__ __launch_bounds__(128) void gemm_wmma_kernel(
    const float* __restrict__ A1, const float* __restrict__ W,
    __half* __restrict__ outv, int n) {
    constexpr int LDW = GBN + 8;
    constexpr int LDA = K + 8;
    constexpr int LDS_ = GBN + 4;
    extern __shared__ char smraw[];
    __half* Ws = (__half*)smraw;
    __half* As = (__half*)(smraw + (size_t)K * LDW * 2);
    float*  St = (float*)(smraw + (size_t)K * LDW * 2);

    const int t = threadIdx.x;
    const int w = t >> 5;
    const int row0 = blockIdx.x * GBM;
    const int bn0 = blockIdx.y * GBN;

    for (int idx = t; idx < K * GBN / 4; idx += 128) {
        int k = idx / (GBN / 4);
        int j = (idx % (GBN / 4)) * 4;
        const float* src = W + (size_t)k * C + bn0 + j;
        Ws[k * LDW + j + 0] = __float2half(src[0]);
        Ws[k * LDW + j + 1] = __float2half(src[1]);
        Ws[k * LDW + j + 2] = __float2half(src[2]);
        Ws[k * LDW + j + 3] = __float2half(src[3]);
    }
    constexpr int CPR = K / 8;
#pragma unroll
    for (int it = 0; it < GBM * CPR / 128; it++) {
        int cidx = t + it * 128;
        int r = cidx / CPR;
        int kq = (cidx % CPR) * 8;
        int gr = row0 + r;
        __half hv[8];
        if (gr < n) {
            float s = g_dinv[gr];
            const float* p = A1 + (size_t)gr * K + kq;
#pragma unroll
            for (int q = 0; q < 8; q++) hv[q] = __float2half(s * p[q]);
        } else {
#pragma unroll
            for (int q = 0; q < 8; q++) hv[q] = __float2half(0.f);
        }
        *(uint4*)&As[r * LDA + kq] = *(uint4*)hv;
    }
    __syncthreads();

    wmma::fragment<wmma::accumulator, 16, 16, 16, float> acc[2][4];
#pragma unroll
    for (int i = 0; i < 2; i++)
#pragma unroll
        for (int j = 0; j < 4; j++) wmma::fill_fragment(acc[i][j], 0.f);

    for (int k = 0; k < K; k += 16) {
        wmma::fragment<wmma::matrix_a, 16, 16, 16, __half, wmma::row_major> af[2];
        wmma::fragment<wmma::matrix_b, 16, 16, 16, __half, wmma::row_major> bfr[4];
        wmma::load_matrix_sync(af[0], As + (w * 32 + 0) * LDA + k, LDA);
        wmma::load_matrix_sync(af[1], As + (w * 32 + 16) * LDA + k, LDA);
#pragma unroll
        for (int j = 0; j < 4; j++)
            wmma::load_matrix_sync(bfr[j], Ws + k * LDW + j * 16, LDW);
#pragma unroll
        for (int i = 0; i < 2; i++)
#pragma unroll
            for (int j = 0; j < 4; j++)
                wmma::mma_sync(acc[i][j], af[i], bfr[j], acc[i][j]);
    }
    __syncthreads();
#pragma unroll
    for (int i = 0; i < 2; i++)
#pragma unroll
        for (int j = 0; j < 4; j++)
            wmma::store_matrix_sync(St + (w * 32 + i * 16) * LDS_ + j * 16,
                                    acc[i][j], LDS_, wmma::mem_row_major);
    __syncthreads();

    const int lane = t & 7;
    const int rsub = t >> 3;
#pragma unroll
    for (int g = 0; g < 8; g++) {
        int r = g * 16 + rsub;
        int gr = row0 + r;
        if (gr >= n) continue;
        const float* sp = St + r * LDS_ + lane * 8;
        __half hv[8];
#pragma unroll
        for (int q = 0; q < 8; q++) hv[q] = __float2half(sp[q]);
        *(uint4*)(outv + (size_t)gr * C + bn0 + lane * 8) = *(uint4*)hv;
    }
}

// ---------------- plain aggregation (h2 producer) ----------------
template <int D, bool RELU>
__global__ __launch_bounds__(256) void agg_kernel(
    const __half* __restrict__ hs, const float* __restrict__ bias,
    __half* __restrict__ out, int n) {
    constexpr int LPN = D / 8;
    int idx = blockIdx.x * blockDim.x + threadIdx.x;
    int v = idx / LPN;
    int lane = idx % LPN;
    if (v >= n) return;
    int c = lane * 8;
    float acc[8];
    gather8(hs, v, c, D, acc);
    float s = g_dinv[v];
    float4 b0 = *(const float4*)(bias + c);
    float4 b1 = *(const float4*)(bias + c + 4);
    float bb[8] = {b0.x, b0.y, b0.z, b0.w, b1.x, b1.y, b1.z, b1.w};
    __half hv[8];
#pragma unroll
    for (int q = 0; q < 8; q++) {
        float r = s * acc[q] + bb[q];
        if (RELU) r = fmaxf(r, 0.f);
        hv[q] = __float2half(r);
    }
    *(uint4*)(out + (size_t)v * D + c) = *(uint4*)hv;
}

// ---------------- host launch ----------------
extern "C" void kernel_launch(void* const* d_in, const int* in_sizes, int n_in,
                              void* d_out, int out_size) {
    const float* x   = (const float*)d_in[0];
    const float* y   = (const float*)d_in[1];
    const int*   ei  = (const int*)d_in[2];
    const float* Wg1 = (const float*)d_in[3];
    const float* bg1 = (const float*)d_in[4];
    const float* Wg2 = (const float*)d_in[5];
    const float* bg2 = (const float*)d_in[6];
    const float* Wl  = (const float*)d_in[7];
    const float* bl  = (const float*)d_in[8];
    const float* Wf  = (const float*)d_in[9];
    const float* bf  = (const float*)d_in[10];
    float* out = (float*)d_out;

    int n = in_sizes[0] / 128;
    int e = in_sizes[2] / 2;
    const int* src = ei;
    const int* dst = ei + e;

    __half *hA, *hB, *hH2;
    cudaGetSymbolAddress((void**)&hA, g_hA);
    cudaGetSymbolAddress((void**)&hB, g_hB);
    cudaGetSymbolAddress((void**)&hH2, g_hH2);

    // smem sizes
    auto gsm = [](int K) -> size_t {
        size_t WsB = (size_t)K * (GBN + 8) * 2;
        size_t AsB = (size_t)GBM * (K + 8) * 2;
        size_t StB = (size_t)GBM * (GBN + 4) * 4;
        return WsB + (AsB > StB ? AsB : StB);
    };
    size_t sgF = gsm(128), sgL = gsm(64);
    size_t sf64, sf128, sfin;
    {
        size_t a = (size_t)128 * (64 + 8) * 2 + (size_t)64 * (64 + 8) * 2;
        size_t s = (size_t)128 * (64 + 4) * 4;
        sf64 = a > s ? a : s;
        a = (size_t)128 * (128 + 8) * 2 + (size_t)128 * (128 + 8) * 2;
        s = (size_t)128 * (128 + 4) * 4;
        sf128 = a > s ? a : s;
        a = (size_t)128 * (192 + 8) * 2 + (size_t)192 * (64 + 8) * 2;
        s = (size_t)128 * (64 + 4) * 4;
        sfin = a > s ? a : s;
    }
    cudaFuncSetAttribute((const void*)gemm_wmma_kernel<128, 128>,
                         cudaFuncAttributeMaxDynamicSharedMemorySize, (int)sgF);
    cudaFuncSetAttribute((const void*)gemm_wmma_kernel<64, 64>,
                         cudaFuncAttributeMaxDynamicSharedMemorySize, (int)sgL);
    cudaFuncSetAttribute((const void*)fused_agg_gemm_kernel<64>,
                         cudaFuncAttributeMaxDynamicSharedMemorySize, (int)sf64);
    cudaFuncSetAttribute((const void*)fused_agg_gemm_kernel<128>,
                         cudaFuncAttributeMaxDynamicSharedMemorySize, (int)sf128);
    cudaFuncSetAttribute((const void*)final_fused_kernel,
                         cudaFuncAttributeMaxDynamicSharedMemorySize, (int)sfin);

    int nb_n = (n + 255) / 256;
    int nb_e = (e + 255) / 256;
    int nb_scan = (n + 1023) / 1024;

    // CSR + dinv
    zero_counts_kernel<<<nb_n, 256>>>(n);
    count_edges_kernel<<<nb_e, 256>>>(dst, e);
    scan1_kernel<<<nb_scan, 1024>>>(n);
    scan2_kernel<<<1, 128>>>(nb_scan);
    scan3_kernel<<<(n + 1023) / 1024, 1024>>>(n, nb_scan);
    scatter_edges_kernel<<<nb_e, 256>>>(src, dst, e);

    int rb = (n + 127) / 128;
    dim3 gF(rb, 2);
    dim3 gL(rb, 1);
    int agg128_blocks = (int)(((size_t)n * 16 + 255) / 256);

    // feature branch: x -> hA -> (fused agg+Wg2) hB -> (agg) h2
    gemm_wmma_kernel<128, 128><<<gF, 128, sgF>>>(x, Wg1, hA, n);
    fused_agg_gemm_kernel<128><<<rb, 256, sf128>>>(hA, bg1, Wg2, hB, n);
    agg_kernel<128, false><<<agg128_blocks, 256>>>(hB, bg2, hH2, n);

    // label branch: y -> hA; 9 fused layers; ends in hB
    gemm_wmma_kernel<64, 64><<<gL, 128, sgL>>>(y, Wl, hA, n);
    for (int j = 0; j < 9; j++) {
        const __half* in = (j % 2 == 0) ? hA : hB;
        __half* o = (j % 2 == 0) ? hB : hA;
        fused_agg_gemm_kernel<64><<<rb, 256, sf64>>>(
            in, bl + (size_t)j * 64, Wl + (size_t)(j + 1) * 64 * 64, o, n);
    }

    // final: agg(label, bl[9]) + concat(h2) @ Wf + bf -> sigmoid
    final_fused_kernel<<<rb, 256, sfin>>>(hB, bl + (size_t)9 * 64, hH2, Wf, bf,
                                          out, n);
}

// round 5
// speedup vs baseline: 1.0316x; 1.0316x over previous
#include <cuda_runtime.h>
#include <cuda_fp16.h>
#include <mma.h>
#include <math.h>

using namespace nvcuda;

#define NMAX 100000
#define EMAX 1600000

// ---------------- device scratch ----------------
__device__ float  g_dinv[NMAX];
__device__ int    g_cnt[NMAX];
__device__ int    g_fill[NMAX];
__device__ int    g_rowptr[NMAX + 1];
__device__ int    g_bsum[256];
__device__ int    g_col[EMAX];
// feature branch buffers (d=128)
__device__ __half g_hA[(size_t)NMAX * 128];
__device__ __half g_hB[(size_t)NMAX * 128];
__device__ __half g_hH2[(size_t)NMAX * 128];
// label branch buffers (d=64)
__device__ __half g_hC[(size_t)NMAX * 64];
__device__ __half g_hD[(size_t)NMAX * 64];

// ---------------- CSR build ----------------
__global__ void zero_counts_kernel(int n) {
    int i = blockIdx.x * blockDim.x + threadIdx.x;
    if (i < n) { g_cnt[i] = 0; g_fill[i] = 0; }
}

__global__ void count_edges_kernel(const int* __restrict__ dst, int e) {
    int i = blockIdx.x * blockDim.x + threadIdx.x;
    if (i < e) atomicAdd(&g_cnt[dst[i]], 1);
}

__global__ void scan1_kernel(int n) {
    __shared__ int s[1024];
    int tid = threadIdx.x;
    int i = blockIdx.x * 1024 + tid;
    int v = (i < n) ? g_cnt[i] : 0;
    s[tid] = v;
    __syncthreads();
    for (int off = 1; off < 1024; off <<= 1) {
        int t2 = (tid >= off) ? s[tid - off] : 0;
        __syncthreads();
        s[tid] += t2;
        __syncthreads();
    }
    if (i < n) {
        g_rowptr[i] = s[tid] - v;
        g_dinv[i] = rsqrtf((float)(v + 1));
    }
    if (tid == 1023) g_bsum[blockIdx.x] = s[1023];
}

__global__ void scan2_kernel(int nb) {
    __shared__ int s[128];
    int tid = threadIdx.x;
    int v = (tid < nb) ? g_bsum[tid] : 0;
    s[tid] = v;
    __syncthreads();
    for (int off = 1; off < 128; off <<= 1) {
        int t2 = (tid >= off) ? s[tid - off] : 0;
        __syncthreads();
        s[tid] += t2;
        __syncthreads();
    }
    if (tid < nb) g_bsum[tid] = s[tid] - v;
    if (tid == 127) g_bsum[nb] = s[127];
}

__global__ void scan3_kernel(int n, int nb) {
    int i = blockIdx.x * blockDim.x + threadIdx.x;
    if (i < n) g_rowptr[i] += g_bsum[i >> 10];
    if (i == 0) g_rowptr[n] = g_bsum[nb];
}

__global__ void scatter_edges_kernel(const int* __restrict__ src,
                                     const int* __restrict__ dst, int e) {
    int i = blockIdx.x * blockDim.x + threadIdx.x;
    if (i < e) {
        int d = dst[i];
        int p = g_rowptr[d] + atomicAdd(&g_fill[d], 1);
        g_col[p] = src[i];
    }
}

// ---------------- wmma GEMM ----------------
// out tile [BM=128 rows] x [BN=64 cols].  4 warps, each warp: 32 rows x 64 cols.
// A source: rows from A1 (TA elements, width K1) for k<K1, A2 (half, width K-K1)
// for k>=K1.  EPI 0: A rows pre-scaled by dinv, output half.
// EPI 1: output = sigmoid(acc + bias), fp32.
#define GBM 128
#define GBN 64

template <int K, int C, int K1, int EPI, typename TA>
__global__ __launch_bounds__(128) void gemm_wmma_kernel(
    const TA* __restrict__ A1, const __half* __restrict__ A2,
    const float* __restrict__ W, const float* __restrict__ bias,
    void* __restrict__ outv, int n) {
    constexpr int LDW = GBN + 8;   // half
    constexpr int LDA = K + 8;     // half
    constexpr int LDS_ = GBN + 4;  // float staging
    extern __shared__ char smraw[];
    __half* Ws = (__half*)smraw;
    __half* As = (__half*)(smraw + (size_t)K * LDW * 2);
    float*  St = (float*)(smraw + (size_t)K * LDW * 2);

    const int t = threadIdx.x;
    const int w = t >> 5;
    const int row0 = blockIdx.x * GBM;
    const int bn0 = blockIdx.y * GBN;

    // load W tile [K][BN] fp32 -> half
    for (int idx = t; idx < K * GBN / 4; idx += 128) {
        int k = idx / (GBN / 4);
        int j = (idx % (GBN / 4)) * 4;
        const float* src = W + (size_t)k * C + bn0 + j;
        Ws[k * LDW + j + 0] = __float2half(src[0]);
        Ws[k * LDW + j + 1] = __float2half(src[1]);
        Ws[k * LDW + j + 2] = __float2half(src[2]);
        Ws[k * LDW + j + 3] = __float2half(src[3]);
    }

    // load A tile [BM][K] (pre-scaled by dinv when EPI==0)
    constexpr int CPR = K / 8;  // 8-elem chunks per row
#pragma unroll
    for (int it = 0; it < GBM * CPR / 128; it++) {
        int cidx = t + it * 128;
        int r = cidx / CPR;
        int kq = (cidx % CPR) * 8;
        int gr = row0 + r;
        float vals[8];
        if (gr < n) {
            float s = (EPI == 0) ? g_dinv[gr] : 1.0f;
            if (kq < K1) {
                const TA* p = A1 + (size_t)gr * K1 + kq;
#pragma unroll
                for (int q = 0; q < 8; q++) vals[q] = s * (float)p[q];
            } else {
                const __half* p = A2 + (size_t)gr * (K - K1) + (kq - K1);
#pragma unroll
                for (int q = 0; q < 8; q++) vals[q] = s * __half2float(p[q]);
            }
        } else {
#pragma unroll
            for (int q = 0; q < 8; q++) vals[q] = 0.f;
        }
        __half* dstp = As + r * LDA + kq;
#pragma unroll
        for (int q = 0; q < 8; q++) dstp[q] = __float2half(vals[q]);
    }
    __syncthreads();

    wmma::fragment<wmma::accumulator, 16, 16, 16, float> acc[2][4];
#pragma unroll
    for (int i = 0; i < 2; i++)
#pragma unroll
        for (int j = 0; j < 4; j++) wmma::fill_fragment(acc[i][j], 0.f);

    for (int k = 0; k < K; k += 16) {
        wmma::fragment<wmma::matrix_a, 16, 16, 16, __half, wmma::row_major> af[2];
        wmma::fragment<wmma::matrix_b, 16, 16, 16, __half, wmma::row_major> bfr[4];
        wmma::load_matrix_sync(af[0], As + (w * 32 + 0) * LDA + k, LDA);
        wmma::load_matrix_sync(af[1], As + (w * 32 + 16) * LDA + k, LDA);
#pragma unroll
        for (int j = 0; j < 4; j++)
            wmma::load_matrix_sync(bfr[j], Ws + k * LDW + j * 16, LDW);
#pragma unroll
        for (int i = 0; i < 2; i++)
#pragma unroll
            for (int j = 0; j < 4; j++)
                wmma::mma_sync(acc[i][j], af[i], bfr[j], acc[i][j]);
    }

    __syncthreads();  // done reading As; staging aliases it
#pragma unroll
    for (int i = 0; i < 2; i++)
#pragma unroll
        for (int j = 0; j < 4; j++)
            wmma::store_matrix_sync(St + (w * 32 + i * 16) * LDS_ + j * 16,
                                    acc[i][j], LDS_, wmma::mem_row_major);
    __syncthreads();

    // epilogue: 128 threads = 16 rows x 8 lanes, 8 row-groups
    const int lane = t & 7;
    const int rsub = t >> 3;
#pragma unroll
    for (int g = 0; g < 8; g++) {
        int r = g * 16 + rsub;
        int gr = row0 + r;
        if (gr >= n) continue;
        const float* sp = St + r * LDS_ + lane * 8;
        if (EPI == 0) {
            __half* outp = (__half*)outv + (size_t)gr * C + bn0 + lane * 8;
            __half hv[8];
#pragma unroll
            for (int q = 0; q < 8; q++) hv[q] = __float2half(sp[q]);
            *(uint4*)outp = *(uint4*)hv;
        } else {
            float* outp = (float*)outv + (size_t)gr * C + bn0 + lane * 8;
            const float* bp = bias + bn0 + lane * 8;
            float ov[8];
#pragma unroll
            for (int q = 0; q < 8; q++)
                ov[q] = 1.f / (1.f + __expf(-(sp[q] + bp[q])));
            *(float4*)outp = *(float4*)ov;
            *(float4*)(outp + 4) = *(float4*)(ov + 4);
        }
    }
}

// ---------------- aggregation (half msgs, fp32 accumulate) ----------------
template <int D, bool RELU>
__global__ __launch_bounds__(256) void agg_kernel(
    const __half* __restrict__ hs, const float* __restrict__ bias,
    __half* __restrict__ out, int n) {
    constexpr int LPN = D / 8;  // lanes per node, 8 halfs each
    int idx = blockIdx.x * blockDim.x + threadIdx.x;
    int v = idx / LPN;
    int lane = idx % LPN;
    if (v >= n) return;
    int c = lane * 8;
    const uint4* base = (const uint4*)hs;
    size_t selfidx = ((size_t)v * D + c) >> 3;

    float acc[8];
    {
        uint4 sv = base[selfidx];
        const __half2* h = (const __half2*)&sv;
#pragma unroll
        for (int q = 0; q < 4; q++) {
            float2 f = __half22float2(h[q]);
            acc[2 * q] = f.x; acc[2 * q + 1] = f.y;
        }
    }
    float acc2[8] = {0, 0, 0, 0, 0, 0, 0, 0};
    int beg = g_rowptr[v], end = g_rowptr[v + 1];
    int e = beg;
    for (; e + 1 < end; e += 2) {
        int u0 = g_col[e], u1 = g_col[e + 1];
        uint4 m0 = base[((size_t)u0 * D + c) >> 3];
        uint4 m1 = base[((size_t)u1 * D + c) >> 3];
        const __half2* h0 = (const __half2*)&m0;
        const __half2* h1 = (const __half2*)&m1;
#pragma unroll
        for (int q = 0; q < 4; q++) {
            float2 f0 = __half22float2(h0[q]);
            float2 f1 = __half22float2(h1[q]);
            acc[2 * q] += f0.x; acc2[2 * q] += f1.x;
            acc[2 * q + 1] += f0.y; acc2[2 * q + 1] += f1.y;
        }
    }
    if (e < end) {
        int u = g_col[e];
        uint4 m = base[((size_t)u * D + c) >> 3];
        const __half2* h = (const __half2*)&m;
#pragma unroll
        for (int q = 0; q < 4; q++) {
            float2 f = __half22float2(h[q]);
            acc[2 * q] += f.x;
            acc[2 * q + 1] += f.y;
        }
    }
    float s = g_dinv[v];
    float4 b0 = *(const float4*)(bias + c);
    float4 b1 = *(const float4*)(bias + c + 4);
    float bb[8] = {b0.x, b0.y, b0.z, b0.w, b1.x, b1.y, b1.z, b1.w};
    __half hv[8];
#pragma unroll
    for (int q = 0; q < 8; q++) {
        float r = s * (acc[q] + acc2[q]) + bb[q];
        if (RELU) r = fmaxf(r, 0.f);
        hv[q] = __float2half(r);
    }
    ((uint4*)out)[selfidx] = *(uint4*)hv;
}

// ---------------- host launch ----------------
extern "C" void kernel_launch(void* const* d_in, const int* in_sizes, int n_in,
                              void* d_out, int out_size) {
    const float* x   = (const float*)d_in[0];
    const float* y   = (const float*)d_in[1];
    const int*   ei  = (const int*)d_in[2];
    const float* Wg1 = (const float*)d_in[3];
    const float* bg1 = (const float*)d_in[4];
    const float* Wg2 = (const float*)d_in[5];
    const float* bg2 = (const float*)d_in[6];
    const float* Wl  = (const float*)d_in[7];
    const float* bl  = (const float*)d_in[8];
    const float* Wf  = (const float*)d_in[9];
    const float* bf  = (const float*)d_in[10];
    float* out = (float*)d_out;

    int n = in_sizes[0] / 128;
    int e = in_sizes[2] / 2;
    const int* src = ei;
    const int* dst = ei + e;

    __half *hA, *hB, *hH2, *hC, *hD;
    cudaGetSymbolAddress((void**)&hA, g_hA);
    cudaGetSymbolAddress((void**)&hB, g_hB);
    cudaGetSymbolAddress((void**)&hH2, g_hH2);
    cudaGetSymbolAddress((void**)&hC, g_hC);
    cudaGetSymbolAddress((void**)&hD, g_hD);

    static cudaStream_t s1 = nullptr, s2 = nullptr;
    static cudaEvent_t eDinv = nullptr, eCsr = nullptr, eFeat = nullptr,
                       eLab = nullptr;
    static bool attr_done = false;

    auto smem_sz = [](int K) -> size_t {
        size_t WsB = (size_t)K * (GBN + 8) * 2;
        size_t AsB = (size_t)GBM * (K + 8) * 2;
        size_t StB = (size_t)GBM * (GBN + 4) * 4;
        return WsB + (AsB > StB ? AsB : StB);
    };
    size_t sm64 = smem_sz(64), sm128 = smem_sz(128), sm192 = smem_sz(192);

    if (!attr_done) {
        cudaStreamCreateWithFlags(&s1, cudaStreamNonBlocking);
        cudaStreamCreateWithFlags(&s2, cudaStreamNonBlocking);
        cudaEventCreateWithFlags(&eDinv, cudaEventDisableTiming);
        cudaEventCreateWithFlags(&eCsr, cudaEventDisableTiming);
        cudaEventCreateWithFlags(&eFeat, cudaEventDisableTiming);
        cudaEventCreateWithFlags(&eLab, cudaEventDisableTiming);
        cudaFuncSetAttribute((const void*)gemm_wmma_kernel<128, 128, 128, 0, float>,
                             cudaFuncAttributeMaxDynamicSharedMemorySize, (int)sm128);
        cudaFuncSetAttribute((const void*)gemm_wmma_kernel<128, 128, 128, 0, __half>,
                             cudaFuncAttributeMaxDynamicSharedMemorySize, (int)sm128);
        cudaFuncSetAttribute((const void*)gemm_wmma_kernel<64, 64, 64, 0, float>,
                             cudaFuncAttributeMaxDynamicSharedMemorySize, (int)sm64);
        cudaFuncSetAttribute((const void*)gemm_wmma_kernel<64, 64, 64, 0, __half>,
                             cudaFuncAttributeMaxDynamicSharedMemorySize, (int)sm64);
        cudaFuncSetAttribute((const void*)gemm_wmma_kernel<192, 64, 128, 1, __half>,
                             cudaFuncAttributeMaxDynamicSharedMemorySize, (int)sm192);
        attr_done = true;
    }

    int nb_n = (n + 255) / 256;
    int nb_e = (e + 255) / 256;
    int nb_scan = (n + 1023) / 1024;

    // ---- CSR + dinv on stream 0 ----
    zero_counts_kernel<<<nb_n, 256>>>(n);
    count_edges_kernel<<<nb_e, 256>>>(dst, e);
    scan1_kernel<<<nb_scan, 1024>>>(n);
    cudaEventRecord(eDinv, 0);  // dinv ready (first GEMMs only need this)
    scan2_kernel<<<1, 128>>>(nb_scan);
    scan3_kernel<<<(n + 1023) / 1024, 1024>>>(n, nb_scan);
    scatter_edges_kernel<<<nb_e, 256>>>(src, dst, e);
    cudaEventRecord(eCsr, 0);   // adjacency ready

    int rb = (n + GBM - 1) / GBM;
    dim3 g128(rb, 2);
    dim3 g64(rb, 1);
    int agg128_blocks = (int)(((size_t)n * 16 + 255) / 256);
    int agg64_blocks  = (int)(((size_t)n * 8 + 255) / 256);

    // ---- feature branch on s1 ----
    cudaStreamWaitEvent(s1, eDinv, 0);
    gemm_wmma_kernel<128, 128, 128, 0, float><<<g128, 128, sm128, s1>>>(
        x, nullptr, Wg1, nullptr, hA, n);
    cudaStreamWaitEvent(s1, eCsr, 0);
    agg_kernel<128, true><<<agg128_blocks, 256, 0, s1>>>(hA, bg1, hB, n);
    gemm_wmma_kernel<128, 128, 128, 0, __half><<<g128, 128, sm128, s1>>>(
        hB, nullptr, Wg2, nullptr, hA, n);
    agg_kernel<128, false><<<agg128_blocks, 256, 0, s1>>>(hA, bg2, hH2, n);
    cudaEventRecord(eFeat, s1);

    // ---- label branch on s2 ----
    cudaStreamWaitEvent(s2, eDinv, 0);
    gemm_wmma_kernel<64, 64, 64, 0, float><<<g64, 128, sm64, s2>>>(
        y, nullptr, Wl, nullptr, hC, n);
    cudaStreamWaitEvent(s2, eCsr, 0);
    agg_kernel<64, true><<<agg64_blocks, 256, 0, s2>>>(hC, bl, hD, n);
    for (int j = 1; j < 10; j++) {
        gemm_wmma_kernel<64, 64, 64, 0, __half><<<g64, 128, sm64, s2>>>(
            hD, nullptr, Wl + (size_t)j * 64 * 64, nullptr, hC, n);
        if (j < 9)
            agg_kernel<64, true><<<agg64_blocks, 256, 0, s2>>>(
                hC, bl + (size_t)j * 64, hD, n);
        else
            agg_kernel<64, false><<<agg64_blocks, 256, 0, s2>>>(
                hC, bl + (size_t)j * 64, hD, n);
    }
    cudaEventRecord(eLab, s2);

    // ---- join + final fused layer on stream 0 ----
    cudaStreamWaitEvent(0, eFeat, 0);
    cudaStreamWaitEvent(0, eLab, 0);
    gemm_wmma_kernel<192, 64, 128, 1, __half><<<g64, 128, sm192>>>(
        hH2, hD, Wf, bf, out, n);
}